// round 10
// baseline (speedup 1.0000x reference)
#include <cuda_runtime.h>
#include <cstdint>

// Problem constants
#define B_   8
#define H_   224
#define HW_  (H_*H_)          // 50176
#define OC_  32
#define NH_  8
#define HD_  4
#define NPIX (B_*HW_)         // 401408
#define X1_N (B_*OC_*HW_)     // 12845056
#define QKV_N (B_*96*HW_)     // 38535168
#define ATT_N (B_*NH_*HD_*H_*H_) // 12845056

// Scratch (static device globals; no allocation allowed)
__device__ float g_x1[X1_N];
__device__ float g_qkv[QKV_N];
__device__ float g_A2[X1_N];
__device__ int   g_jidx[B_*NH_*HD_*H_];   // 57344
__device__ float g_wc[32*32];
__device__ float g_bc[32];
__device__ float g_sum[32];
__device__ float g_sq[32];

// ---------------------------------------------------------------- prep
__global__ void k_prep(const float* __restrict__ upd_w, const float* __restrict__ proj_w,
                       const float* __restrict__ proj_b, const float* __restrict__ upd_b) {
    int t = threadIdx.x;            // 1024 threads
    int o = t >> 5, c = t & 31;
    float s = 0.f;
    #pragma unroll
    for (int m = 0; m < 32; m++) s += upd_w[o*32+m] * proj_w[m*32+c];
    g_wc[o*32+c] = s;
    if (c == 0) {
        float bsum = upd_b[o];
        #pragma unroll
        for (int m = 0; m < 32; m++) bsum += upd_w[o*32+m] * proj_b[m];
        g_bc[o] = bsum;
    }
    if (t < 32) { g_sum[t] = 0.f; g_sq[t] = 0.f; }
}

// ---------------------------------------------------------------- conv_in: 3->32, 3x3, pad 1 (2 px/thread)
__global__ __launch_bounds__(256) void k_conv_in(const float* __restrict__ x,
                                                 const float* __restrict__ w,
                                                 const float* __restrict__ bias) {
    __shared__ float ws[32*27];
    __shared__ float bs[32];
    int t = threadIdx.x;
    for (int i = t; i < 864; i += 256) ws[i] = w[i];
    if (t < 32) bs[t] = bias[t];
    __syncthreads();
    int p2 = blockIdx.x * 256 + t;            // < NPIX/2 exact
    int pix = p2 * 2;
    int b = pix / HW_; int hw = pix % HW_;
    int h = hw / H_, wd = hw % H_;            // wd even
    float acc0[32], acc1[32];
    #pragma unroll
    for (int o = 0; o < 32; o++) { acc0[o] = bs[o]; acc1[o] = bs[o]; }
    for (int c = 0; c < 3; c++) {
        const float* xc = x + ((size_t)(b*3 + c))*HW_;
        #pragma unroll
        for (int kr = 0; kr < 3; kr++) {
            int ih = h + kr - 1; if (ih < 0 || ih >= H_) continue;
            const float* row = xc + ih*H_;
            float xm1 = (wd - 1 >= 0) ? row[wd-1] : 0.f;
            float x0  = row[wd];
            float x1  = row[wd+1];
            float x2  = (wd + 2 < H_) ? row[wd+2] : 0.f;
            float a0[3] = {xm1, x0, x1};
            float a1[3] = {x0, x1, x2};
            #pragma unroll
            for (int kc = 0; kc < 3; kc++) {
                int wi = c*9 + kr*3 + kc;
                float v0 = a0[kc], v1 = a1[kc];
                #pragma unroll
                for (int o = 0; o < 32; o++) {
                    float wv = ws[o*27 + wi];
                    acc0[o] = fmaf(wv, v0, acc0[o]);
                    acc1[o] = fmaf(wv, v1, acc1[o]);
                }
            }
        }
    }
    #pragma unroll
    for (int o = 0; o < 32; o++)
        *(float2*)&g_x1[((size_t)(b*32 + o)*H_ + h)*H_ + wd] = make_float2(acc0[o], acc1[o]);
}

// ---------------------------------------------------------------- conv_qkv: 32->96, 3x3, pad 1
// 128 thr = 32 rows x 4 col-groups of 8 px; 8 oc per block (grid.y=12).
// Accumulation order (g -> ic -> kr -> kc) identical to the R3 passing kernel
// => q/k outputs bit-identical => argmax unchanged.
__global__ __launch_bounds__(128) void k_conv_qkv(const float* __restrict__ w) {
    __shared__ __align__(16) float ps[8][34][36];
    __shared__ __align__(16) float wsm[8][9][8];   // [ic][tap][oc]
    int t = threadIdx.x;
    int tile = blockIdx.x;                 // 0..391
    int b = tile / 49; int th = (tile % 49) / 7, tw = tile % 7;
    int h0 = th * 32, w0 = tw * 32;
    int oc0 = blockIdx.y * 8;              // 0..11
    int r = t >> 2, cg = t & 3;            // row 0..31, col-group 0..3 (8 px)
    float acc[8][8];
    #pragma unroll
    for (int o = 0; o < 8; o++)
        #pragma unroll
        for (int p = 0; p < 8; p++) acc[o][p] = 0.f;

    int lw = t >> 5, ln = t & 31;          // 4 warps; each loads 2 ics
    for (int g = 0; g < 4; g++) {
        __syncthreads();
        for (int ic = lw; ic < 8; ic += 4) {
            const float* src = g_x1 + (size_t)(b*32 + g*8 + ic) * HW_;
            int bh = h0 - 1, bw = w0 - 1;
            for (int rr = 0; rr < 34; rr++) {
                int ih = bh + rr;
                bool hok = ((unsigned)ih < (unsigned)H_);
                int iw = bw + ln;
                ps[ic][rr][ln] = (hok && (unsigned)iw < (unsigned)H_) ? src[ih*H_ + iw] : 0.f;
                if (ln < 2) {
                    int iw2 = bw + 32 + ln;
                    ps[ic][rr][32 + ln] = (hok && (unsigned)iw2 < (unsigned)H_) ? src[ih*H_ + iw2] : 0.f;
                }
            }
        }
        for (int i = t; i < 576; i += 128) {
            int ic = i / 72; int rem = i % 72; int tap = rem >> 3; int oc = rem & 7;
            wsm[ic][tap][oc] = w[((oc0 + oc)*32 + g*8 + ic)*9 + tap];
        }
        __syncthreads();
        #pragma unroll
        for (int ic = 0; ic < 8; ic++) {
            #pragma unroll
            for (int kr = 0; kr < 3; kr++) {
                float px[10];
                const float2* prow = (const float2*)&ps[ic][r + kr][cg*8];
                #pragma unroll
                for (int q = 0; q < 5; q++) {
                    float2 v = prow[q]; px[2*q] = v.x; px[2*q+1] = v.y;
                }
                #pragma unroll
                for (int kc = 0; kc < 3; kc++) {
                    const float4* wp = (const float4*)wsm[ic][kr*3 + kc];
                    float4 wa = wp[0], wb = wp[1];
                    float wv[8] = {wa.x, wa.y, wa.z, wa.w, wb.x, wb.y, wb.z, wb.w};
                    #pragma unroll
                    for (int o = 0; o < 8; o++)
                        #pragma unroll
                        for (int p = 0; p < 8; p++)
                            acc[o][p] = fmaf(wv[o], px[p + kc], acc[o][p]);
                }
            }
        }
    }
    int hh = h0 + r;
    #pragma unroll
    for (int o = 0; o < 8; o++) {
        float* dst = &g_qkv[((size_t)(b*96 + oc0 + o)*H_ + hh)*H_ + w0 + cg*8];
        *(float4*)dst       = make_float4(acc[o][0], acc[o][1], acc[o][2], acc[o][3]);
        *(float4*)(dst + 4) = make_float4(acc[o][4], acc[o][5], acc[o][6], acc[o][7]);
    }
}

// ---------------------------------------------------------------- attention argmax + one-hot (writes full att rows)
// block = (bnd, i-tile of 32); 256 threads (8 warps); warp handles 4 i rows,
// lanes 0-15 / 16-31 split the w-sum for 16 j's per K chunk.
__global__ __launch_bounds__(256) void k_att(const float* __restrict__ gumbel,
                                             float* __restrict__ att) {
    __shared__ float Qs[32][228];
    __shared__ float Ks[16][228];
    int bnd = blockIdx.x;                 // 0..255 = b*32 + n*4 + d
    int it = blockIdx.y;                  // 0..6
    int b = bnd >> 5; int nd = bnd & 31; int n = nd >> 2; int d = nd & 3;
    const float* qbase = g_qkv + (size_t)(b*96 + n*12 + d) * HW_;
    const float* kbase = g_qkv + (size_t)(b*96 + n*12 + 4 + d) * HW_;
    int t = threadIdx.x; int lane = t & 31; int wid = t >> 5;
    int i0 = it * 32;
    for (int i = t; i < 32*56; i += 256) {
        int rr = i / 56, c4 = i % 56;
        *(float4*)&Qs[rr][c4*4] = ((const float4*)(qbase + (size_t)(i0 + rr)*H_))[c4];
    }
    float best[4]; int bj[4];
    #pragma unroll
    for (int r = 0; r < 4; r++) { best[r] = -1e30f; bj[r] = 0; }

    int jj = lane & 15;
    int wbase = (lane >> 4) * 112;
    for (int jt = 0; jt < H_; jt += 16) {
        __syncthreads();
        for (int i = t; i < 16*56; i += 256) {
            int rr = i / 56, c4 = i % 56;
            *(float4*)&Ks[rr][c4*4] = ((const float4*)(kbase + (size_t)(jt + rr)*H_))[c4];
        }
        __syncthreads();
        float acc[4] = {0.f, 0.f, 0.f, 0.f};
        for (int w = 0; w < 112; w += 4) {
            float4 kv = *(const float4*)&Ks[jj][wbase + w];
            #pragma unroll
            for (int r = 0; r < 4; r++) {
                float4 qv = *(const float4*)&Qs[wid*4 + r][wbase + w];
                acc[r] += kv.x*qv.x + kv.y*qv.y + kv.z*qv.z + kv.w*qv.w;
            }
        }
        int j = jt + jj;
        #pragma unroll
        for (int r = 0; r < 4; r++) {
            float dot = acc[r] + __shfl_xor_sync(0xffffffffu, acc[r], 16);
            int i = i0 + wid*4 + r;
            float v = dot*0.5f + gumbel[((size_t)bnd*H_ + i)*H_ + j];
            if (v > best[r]) { best[r] = v; bj[r] = j; }
        }
    }
    #pragma unroll
    for (int r = 0; r < 4; r++) {
        float v = best[r]; int j = bj[r];
        #pragma unroll
        for (int off = 16; off; off >>= 1) {
            float v2 = __shfl_down_sync(0xffffffffu, v, off);
            int   j2 = __shfl_down_sync(0xffffffffu, j, off);
            if (v2 > v || (v2 == v && j2 < j)) { v = v2; j = j2; }
        }
        int jwin = __shfl_sync(0xffffffffu, j, 0);
        int i = i0 + wid*4 + r;
        if (lane == 0) g_jidx[bnd*H_ + i] = jwin;
        // write the full one-hot row (replaces separate zero kernel)
        float4* row4 = (float4*)(att + ((size_t)bnd*H_ + i)*H_);
        int jf = jwin >> 2, jc = jwin & 3;
        for (int c4 = lane; c4 < 56; c4 += 32) {
            float4 v4 = make_float4(0.f, 0.f, 0.f, 0.f);
            if (c4 == jf) ((float*)&v4)[jc] = 1.0f;
            row4[c4] = v4;
        }
    }
}

// ---------------------------------------------------------------- gather v rows + fused 1x1 convs + BN partial sums
// block per (b, i); 224 threads (one per w)
__global__ __launch_bounds__(224) void k_gather_proj() {
    __shared__ float wcs[1024];
    __shared__ float bcs[32];
    __shared__ int   js[32];
    __shared__ float rs[32][7];
    __shared__ float rq[32][7];
    int b = blockIdx.x / H_; int i = blockIdx.x % H_;
    int t = threadIdx.x;
    for (int k = t; k < 1024; k += 224) wcs[k] = g_wc[k];
    if (t < 32) {
        bcs[t] = g_bc[t];
        js[t] = g_jidx[(b*32 + t)*H_ + i];   // t = n*4+d
    }
    __syncthreads();
    float a[32];
    #pragma unroll
    for (int c = 0; c < 32; c++) {
        int n = c >> 2, d = c & 3;
        a[c] = g_qkv[((size_t)(b*96 + n*12 + 8 + d)*H_ + js[c])*H_ + t];
    }
    float out[32];
    #pragma unroll
    for (int o = 0; o < 32; o++) {
        float s = bcs[o];
        #pragma unroll
        for (int c = 0; c < 32; c++) s += wcs[o*32 + c] * a[c];
        out[o] = s;
        g_A2[((size_t)(b*32 + o)*H_ + i)*H_ + t] = s;
    }
    int wid = t >> 5, lane = t & 31;
    #pragma unroll
    for (int o = 0; o < 32; o++) {
        float s = out[o], q = out[o]*out[o];
        #pragma unroll
        for (int off = 16; off; off >>= 1) {
            s += __shfl_down_sync(0xffffffffu, s, off);
            q += __shfl_down_sync(0xffffffffu, q, off);
        }
        if (lane == 0) { rs[o][wid] = s; rq[o][wid] = q; }
    }
    __syncthreads();
    if (t < 32) {
        float s = 0.f, q = 0.f;
        #pragma unroll
        for (int k = 0; k < 7; k++) { s += rs[t][k]; q += rq[t][k]; }
        atomicAdd(&g_sum[t], s);
        atomicAdd(&g_sq[t], q);
    }
}

// ---------------------------------------------------------------- BN + SiLU + residual
__global__ __launch_bounds__(256) void k_final(const float* __restrict__ gamma,
                                               const float* __restrict__ beta,
                                               float* __restrict__ outp) {
    int idx = blockIdx.x * 256 + threadIdx.x;   // < X1_N exact
    int c = (idx / HW_) & 31;
    const float inv_n = 1.f / (float)NPIX;
    float mean = g_sum[c] * inv_n;
    float var = g_sq[c] * inv_n - mean*mean;
    float v = (g_A2[idx] - mean) * rsqrtf(var + 1e-5f) * gamma[c] + beta[c];
    v = v / (1.f + expf(-v));
    outp[idx] = v + g_x1[idx];
}

// ---------------------------------------------------------------- launch
extern "C" void kernel_launch(void* const* d_in, const int* in_sizes, int n_in,
                              void* d_out, int out_size) {
    const float* x      = (const float*)d_in[0];
    const float* gumbel = (const float*)d_in[1];
    const float* in_w   = (const float*)d_in[2];
    const float* in_b   = (const float*)d_in[3];
    const float* qkv_w  = (const float*)d_in[4];
    const float* proj_w = (const float*)d_in[5];
    const float* proj_b = (const float*)d_in[6];
    const float* upd_w  = (const float*)d_in[7];
    const float* upd_b  = (const float*)d_in[8];
    const float* bn_g   = (const float*)d_in[9];
    const float* bn_b   = (const float*)d_in[10];
    float* outp = (float*)d_out;
    float* att  = outp + X1_N;                 // (out, att) concatenated

    k_prep<<<1, 1024>>>(upd_w, proj_w, proj_b, upd_b);
    k_conv_in<<<NPIX/2/256, 256>>>(x, in_w, in_b);
    k_conv_qkv<<<dim3(392, 12), 128>>>(qkv_w);
    k_att<<<dim3(256, 7), 256>>>(gumbel, att);
    k_gather_proj<<<B_*H_, 224>>>();
    k_final<<<X1_N/256, 256>>>(bn_g, bn_b, outp);
}

// round 12
// speedup vs baseline: 1.5465x; 1.5465x over previous
#include <cuda_runtime.h>
#include <cstdint>

// Problem constants
#define B_   8
#define H_   224
#define HW_  (H_*H_)          // 50176
#define OC_  32
#define NH_  8
#define HD_  4
#define NPIX (B_*HW_)         // 401408
#define X1_N (B_*OC_*HW_)     // 12845056
#define QKV_N (B_*96*HW_)     // 38535168
#define ATT_N (B_*NH_*HD_*H_*H_) // 12845056

// Scratch (static device globals; no allocation allowed)
__device__ float g_x1[X1_N];
__device__ float g_qkv[QKV_N];
__device__ float g_A2[X1_N];
__device__ int   g_jidx[B_*NH_*HD_*H_];   // 57344
__device__ float g_wc[32*32];
__device__ float g_bc[32];
__device__ float g_sum[32];
__device__ float g_sq[32];

// ---------------------------------------------------------------- prep
__global__ void k_prep(const float* __restrict__ upd_w, const float* __restrict__ proj_w,
                       const float* __restrict__ proj_b, const float* __restrict__ upd_b) {
    int t = threadIdx.x;            // 1024 threads
    int o = t >> 5, c = t & 31;
    float s = 0.f;
    #pragma unroll
    for (int m = 0; m < 32; m++) s += upd_w[o*32+m] * proj_w[m*32+c];
    g_wc[o*32+c] = s;
    if (c == 0) {
        float bsum = upd_b[o];
        #pragma unroll
        for (int m = 0; m < 32; m++) bsum += upd_w[o*32+m] * proj_b[m];
        g_bc[o] = bsum;
    }
    if (t < 32) { g_sum[t] = 0.f; g_sq[t] = 0.f; }
}

// ---------------------------------------------------------------- conv_in: 3->32, 3x3, pad 1 (2 px/thread)
__global__ __launch_bounds__(256) void k_conv_in(const float* __restrict__ x,
                                                 const float* __restrict__ w,
                                                 const float* __restrict__ bias) {
    __shared__ float ws[32*27];
    __shared__ float bs[32];
    int t = threadIdx.x;
    for (int i = t; i < 864; i += 256) ws[i] = w[i];
    if (t < 32) bs[t] = bias[t];
    __syncthreads();
    int p2 = blockIdx.x * 256 + t;            // < NPIX/2 exact
    int pix = p2 * 2;
    int b = pix / HW_; int hw = pix % HW_;
    int h = hw / H_, wd = hw % H_;            // wd even
    float acc0[32], acc1[32];
    #pragma unroll
    for (int o = 0; o < 32; o++) { acc0[o] = bs[o]; acc1[o] = bs[o]; }
    for (int c = 0; c < 3; c++) {
        const float* xc = x + ((size_t)(b*3 + c))*HW_;
        #pragma unroll
        for (int kr = 0; kr < 3; kr++) {
            int ih = h + kr - 1; if (ih < 0 || ih >= H_) continue;
            const float* row = xc + ih*H_;
            float xm1 = (wd - 1 >= 0) ? row[wd-1] : 0.f;
            float x0  = row[wd];
            float x1  = row[wd+1];
            float x2  = (wd + 2 < H_) ? row[wd+2] : 0.f;
            float a0[3] = {xm1, x0, x1};
            float a1[3] = {x0, x1, x2};
            #pragma unroll
            for (int kc = 0; kc < 3; kc++) {
                int wi = c*9 + kr*3 + kc;
                float v0 = a0[kc], v1 = a1[kc];
                #pragma unroll
                for (int o = 0; o < 32; o++) {
                    float wv = ws[o*27 + wi];
                    acc0[o] = fmaf(wv, v0, acc0[o]);
                    acc1[o] = fmaf(wv, v1, acc1[o]);
                }
            }
        }
    }
    #pragma unroll
    for (int o = 0; o < 32; o++)
        *(float2*)&g_x1[((size_t)(b*32 + o)*H_ + h)*H_ + wd] = make_float2(acc0[o], acc1[o]);
}

// ---------------------------------------------------------------- conv_qkv: 32->96, 3x3, pad 1
// 128 thr = 32 rows x 4 col-groups of 8 px; 8 oc per block (grid.y=12).
__global__ __launch_bounds__(128) void k_conv_qkv(const float* __restrict__ w) {
    __shared__ __align__(16) float ps[8][34][36];
    __shared__ __align__(16) float wsm[8][9][8];   // [ic][tap][oc]
    int t = threadIdx.x;
    int tile = blockIdx.x;                 // 0..391
    int b = tile / 49; int th = (tile % 49) / 7, tw = tile % 7;
    int h0 = th * 32, w0 = tw * 32;
    int oc0 = blockIdx.y * 8;              // 0..11
    int r = t >> 2, cg = t & 3;            // row 0..31, col-group 0..3 (8 px)
    float acc[8][8];
    #pragma unroll
    for (int o = 0; o < 8; o++)
        #pragma unroll
        for (int p = 0; p < 8; p++) acc[o][p] = 0.f;

    int lw = t >> 5, ln = t & 31;          // 4 warps; each loads 2 ics
    for (int g = 0; g < 4; g++) {
        __syncthreads();
        for (int ic = lw; ic < 8; ic += 4) {
            const float* src = g_x1 + (size_t)(b*32 + g*8 + ic) * HW_;
            int bh = h0 - 1, bw = w0 - 1;
            for (int rr = 0; rr < 34; rr++) {
                int ih = bh + rr;
                bool hok = ((unsigned)ih < (unsigned)H_);
                int iw = bw + ln;
                ps[ic][rr][ln] = (hok && (unsigned)iw < (unsigned)H_) ? src[ih*H_ + iw] : 0.f;
                if (ln < 2) {
                    int iw2 = bw + 32 + ln;
                    ps[ic][rr][32 + ln] = (hok && (unsigned)iw2 < (unsigned)H_) ? src[ih*H_ + iw2] : 0.f;
                }
            }
        }
        for (int i = t; i < 576; i += 128) {
            int ic = i / 72; int rem = i % 72; int tap = rem >> 3; int oc = rem & 7;
            wsm[ic][tap][oc] = w[((oc0 + oc)*32 + g*8 + ic)*9 + tap];
        }
        __syncthreads();
        #pragma unroll
        for (int ic = 0; ic < 8; ic++) {
            #pragma unroll
            for (int kr = 0; kr < 3; kr++) {
                float px[10];
                const float2* prow = (const float2*)&ps[ic][r + kr][cg*8];
                #pragma unroll
                for (int q = 0; q < 5; q++) {
                    float2 v = prow[q]; px[2*q] = v.x; px[2*q+1] = v.y;
                }
                #pragma unroll
                for (int kc = 0; kc < 3; kc++) {
                    const float4* wp = (const float4*)wsm[ic][kr*3 + kc];
                    float4 wa = wp[0], wb = wp[1];
                    float wv[8] = {wa.x, wa.y, wa.z, wa.w, wb.x, wb.y, wb.z, wb.w};
                    #pragma unroll
                    for (int o = 0; o < 8; o++)
                        #pragma unroll
                        for (int p = 0; p < 8; p++)
                            acc[o][p] = fmaf(wv[o], px[p + kc], acc[o][p]);
                }
            }
        }
    }
    int hh = h0 + r;
    #pragma unroll
    for (int o = 0; o < 8; o++) {
        float* dst = &g_qkv[((size_t)(b*96 + oc0 + o)*H_ + hh)*H_ + w0 + cg*8];
        *(float4*)dst       = make_float4(acc[o][0], acc[o][1], acc[o][2], acc[o][3]);
        *(float4*)(dst + 4) = make_float4(acc[o][4], acc[o][5], acc[o][6], acc[o][7]);
    }
}

// ---------------------------------------------------------------- attention argmax + one-hot
// Per-(i,j) arithmetic is BIT-IDENTICAL to the round-10 passing kernel:
// same 2-way w-split (112-float halves per lane-half), same contraction
// expression, same commutative half-combine, same first-wins argmax scan in
// ascending j. Only the thread mapping changed: each thread now computes TWO
// j's per 32-row K chunk (j = jt+jj and jt+16+jj), doubling FFMA per K-LDS.
__global__ __launch_bounds__(128) void k_att(const float* __restrict__ gumbel,
                                             float* __restrict__ att) {
    __shared__ float Qs[16][228];
    __shared__ float Ks[32][228];
    int bnd = blockIdx.x;                 // 0..255 = b*32 + n*4 + d
    int it = blockIdx.y;                  // 0..13
    int b = bnd >> 5; int nd = bnd & 31; int n = nd >> 2; int d = nd & 3;
    const float* qbase = g_qkv + (size_t)(b*96 + n*12 + d) * HW_;
    const float* kbase = g_qkv + (size_t)(b*96 + n*12 + 4 + d) * HW_;
    int t = threadIdx.x; int lane = t & 31; int wid = t >> 5;
    int i0 = it * 16;
    for (int i = t; i < 16*56; i += 128) {
        int rr = i / 56, c4 = i % 56;
        *(float4*)&Qs[rr][c4*4] = ((const float4*)(qbase + (size_t)(i0 + rr)*H_))[c4];
    }
    int jj = lane & 15;
    int wbase = (lane >> 4) * 112;
    float best[4]; int bj[4];
    #pragma unroll
    for (int r = 0; r < 4; r++) { best[r] = -1e30f; bj[r] = 0; }

    for (int jt = 0; jt < H_; jt += 32) {
        __syncthreads();
        for (int i = t; i < 32*56; i += 128) {
            int rr = i / 56, c4 = i % 56;
            *(float4*)&Ks[rr][c4*4] = ((const float4*)(kbase + (size_t)(jt + rr)*H_))[c4];
        }
        __syncthreads();
        float acc0[4] = {0.f, 0.f, 0.f, 0.f};
        float acc1[4] = {0.f, 0.f, 0.f, 0.f};
        #pragma unroll 4
        for (int w4 = 0; w4 < 28; w4++) {
            int wof = wbase + w4*4;
            float4 kv0 = *(const float4*)&Ks[jj][wof];
            float4 kv1 = *(const float4*)&Ks[16 + jj][wof];
            #pragma unroll
            for (int r = 0; r < 4; r++) {
                float4 qv = *(const float4*)&Qs[wid*4 + r][wof];
                acc0[r] += kv0.x*qv.x + kv0.y*qv.y + kv0.z*qv.z + kv0.w*qv.w;
                acc1[r] += kv1.x*qv.x + kv1.y*qv.y + kv1.z*qv.z + kv1.w*qv.w;
            }
        }
        #pragma unroll
        for (int r = 0; r < 4; r++) {
            float dot0 = acc0[r] + __shfl_xor_sync(0xffffffffu, acc0[r], 16);
            float dot1 = acc1[r] + __shfl_xor_sync(0xffffffffu, acc1[r], 16);
            int i = i0 + wid*4 + r;
            const float* grow = gumbel + ((size_t)bnd*H_ + i)*H_;
            int j0 = jt + jj;
            float v0 = dot0*0.5f + grow[j0];
            if (v0 > best[r]) { best[r] = v0; bj[r] = j0; }
            int j1 = jt + 16 + jj;
            float v1 = dot1*0.5f + grow[j1];
            if (v1 > best[r]) { best[r] = v1; bj[r] = j1; }
        }
    }
    #pragma unroll
    for (int r = 0; r < 4; r++) {
        float v = best[r]; int j = bj[r];
        #pragma unroll
        for (int off = 16; off; off >>= 1) {
            float v2 = __shfl_down_sync(0xffffffffu, v, off);
            int   j2 = __shfl_down_sync(0xffffffffu, j, off);
            if (v2 > v || (v2 == v && j2 < j)) { v = v2; j = j2; }
        }
        int jwin = __shfl_sync(0xffffffffu, j, 0);
        int i = i0 + wid*4 + r;
        if (lane == 0) g_jidx[bnd*H_ + i] = jwin;
        // write the full one-hot row (no separate zero kernel)
        float4* row4 = (float4*)(att + ((size_t)bnd*H_ + i)*H_);
        int jf = jwin >> 2, jc = jwin & 3;
        for (int c4 = lane; c4 < 56; c4 += 32) {
            float4 v4 = make_float4(0.f, 0.f, 0.f, 0.f);
            if (c4 == jf) ((float*)&v4)[jc] = 1.0f;
            row4[c4] = v4;
        }
    }
}

// ---------------------------------------------------------------- gather v rows + fused 1x1 convs + BN partial sums
// block per (b, i); 224 threads (one per w)
__global__ __launch_bounds__(224) void k_gather_proj() {
    __shared__ float wcs[1024];
    __shared__ float bcs[32];
    __shared__ int   js[32];
    __shared__ float rs[32][7];
    __shared__ float rq[32][7];
    int b = blockIdx.x / H_; int i = blockIdx.x % H_;
    int t = threadIdx.x;
    for (int k = t; k < 1024; k += 224) wcs[k] = g_wc[k];
    if (t < 32) {
        bcs[t] = g_bc[t];
        js[t] = g_jidx[(b*32 + t)*H_ + i];   // t = n*4+d
    }
    __syncthreads();
    float a[32];
    #pragma unroll
    for (int c = 0; c < 32; c++) {
        int n = c >> 2, d = c & 3;
        a[c] = g_qkv[((size_t)(b*96 + n*12 + 8 + d)*H_ + js[c])*H_ + t];
    }
    float out[32];
    #pragma unroll
    for (int o = 0; o < 32; o++) {
        float s = bcs[o];
        #pragma unroll
        for (int c = 0; c < 32; c++) s += wcs[o*32 + c] * a[c];
        out[o] = s;
        g_A2[((size_t)(b*32 + o)*H_ + i)*H_ + t] = s;
    }
    int wid = t >> 5, lane = t & 31;
    #pragma unroll
    for (int o = 0; o < 32; o++) {
        float s = out[o], q = out[o]*out[o];
        #pragma unroll
        for (int off = 16; off; off >>= 1) {
            s += __shfl_down_sync(0xffffffffu, s, off);
            q += __shfl_down_sync(0xffffffffu, q, off);
        }
        if (lane == 0) { rs[o][wid] = s; rq[o][wid] = q; }
    }
    __syncthreads();
    if (t < 32) {
        float s = 0.f, q = 0.f;
        #pragma unroll
        for (int k = 0; k < 7; k++) { s += rs[t][k]; q += rq[t][k]; }
        atomicAdd(&g_sum[t], s);
        atomicAdd(&g_sq[t], q);
    }
}

// ---------------------------------------------------------------- BN + SiLU + residual
__global__ __launch_bounds__(256) void k_final(const float* __restrict__ gamma,
                                               const float* __restrict__ beta,
                                               float* __restrict__ outp) {
    int idx = blockIdx.x * 256 + threadIdx.x;   // < X1_N exact
    int c = (idx / HW_) & 31;
    const float inv_n = 1.f / (float)NPIX;
    float mean = g_sum[c] * inv_n;
    float var = g_sq[c] * inv_n - mean*mean;
    float v = (g_A2[idx] - mean) * rsqrtf(var + 1e-5f) * gamma[c] + beta[c];
    v = v / (1.f + expf(-v));
    outp[idx] = v + g_x1[idx];
}

// ---------------------------------------------------------------- launch
extern "C" void kernel_launch(void* const* d_in, const int* in_sizes, int n_in,
                              void* d_out, int out_size) {
    const float* x      = (const float*)d_in[0];
    const float* gumbel = (const float*)d_in[1];
    const float* in_w   = (const float*)d_in[2];
    const float* in_b   = (const float*)d_in[3];
    const float* qkv_w  = (const float*)d_in[4];
    const float* proj_w = (const float*)d_in[5];
    const float* proj_b = (const float*)d_in[6];
    const float* upd_w  = (const float*)d_in[7];
    const float* upd_b  = (const float*)d_in[8];
    const float* bn_g   = (const float*)d_in[9];
    const float* bn_b   = (const float*)d_in[10];
    float* outp = (float*)d_out;
    float* att  = outp + X1_N;                 // (out, att) concatenated

    k_prep<<<1, 1024>>>(upd_w, proj_w, proj_b, upd_b);
    k_conv_in<<<NPIX/2/256, 256>>>(x, in_w, in_b);
    k_conv_qkv<<<dim3(392, 12), 128>>>(qkv_w);
    k_att<<<dim3(256, 14), 128>>>(gumbel, att);
    k_gather_proj<<<B_*H_, 224>>>();
    k_final<<<X1_N/256, 256>>>(bn_g, bn_b, outp);
}